// round 8
// baseline (speedup 1.0000x reference)
#include <cuda_runtime.h>
#include <cuda_bf16.h>
#include <math.h>

#define BATCH   4096
#define D1      200
#define NREL    500
#define NRELP   512
#define M1      288
#define OC      32
#define FW      9
#define WOUT    392
#define WIN     400
#define VPAD    512
#define FCLEN   12544
#define EPSBN   1e-5f
#define NSPLIT  8
#define ILEN    50
#define FBLK    49

#define G1_ROWB 16
#define G1_COLB 5

// gemm2 v6 geometry
#define RT      32       // rel tile
#define TT      64       // t tile
#define KSPL    12
#define KLEN    24       // 288/12
#define RTILES  16       // 512/32
#define TTILES  7        // ceil(400/64)

// ---------------- device scratch ----------------
__device__ float g_vp[NSPLIT * FCLEN];
__device__ float g_KrelT[M1 * NRELP];      // K-major [k][rel]; pad rels stay zero
__device__ float g_Vmat[M1 * VPAD];        // pad cols stay zero
__device__ float g_qp[KSPL * NREL * WIN];  // K-split partials
__device__ float g_q[NREL * WIN];
__device__ float g_c1[OC];
__device__ float g_scal0;

// ======== K1: v partials (8-way i-split) ================================
__global__ void __launch_bounds__(256) k1_v(
        const float* __restrict__ fcw,
        const float* __restrict__ bn2g, const float* __restrict__ bn2v,
        const float* __restrict__ fc2w) {
    __shared__ float sa[ILEN];
    int tid = threadIdx.x;
    int isp = blockIdx.x / FBLK, fb = blockIdx.x % FBLK;
    if (tid < ILEN) {
        int i = isp * ILEN + tid;
        float s2 = bn2g[i] * rsqrtf(bn2v[i] + EPSBN);
        sa[tid] = s2 * fc2w[i];
    }
    __syncthreads();
    int f = fb * 256 + tid;
    const float* __restrict__ p = fcw + (size_t)isp * ILEN * FCLEN + f;
    float acc = 0.f;
#pragma unroll
    for (int ii = 0; ii < ILEN; ii++)
        acc = fmaf(sa[ii], p[(size_t)ii * FCLEN], acc);
    g_vp[isp * FCLEN + f] = acc;
}

// ======== GEMM1: KrelT[k][rel] = (R @ fc1w^T + b)^T =====================
__global__ void __launch_bounds__(256) gemm1_krel(
        const float* __restrict__ R, const float* __restrict__ fc1w,
        const float* __restrict__ fc1b) {
    __shared__ float Bs[8 * 68];
    __shared__ float As[8 * 36];
    int tid = threadIdx.x;
    int row0 = blockIdx.x * 32, col0 = blockIdx.y * 64;
    int tx = tid & 15, ty = tid >> 4;
    float acc[2][4] = {};
    for (int k0 = 0; k0 < 200; k0 += 8) {
        {
            int m = tid >> 3, kk = tid & 7;
            int gm = row0 + m;
            As[kk * 36 + m] = (gm < NREL) ? R[gm * 200 + k0 + kk] : 0.f;
        }
#pragma unroll
        for (int l = 0; l < 2; l++) {
            int e = l * 256 + tid;
            int n = e >> 3, kk = e & 7;
            int gn = col0 + n;
            Bs[kk * 68 + n] = (gn < M1) ? fc1w[gn * 200 + k0 + kk] : 0.f;
        }
        __syncthreads();
#pragma unroll
        for (int kk = 0; kk < 8; kk++) {
            float a0 = As[kk * 36 + ty * 2];
            float a1 = As[kk * 36 + ty * 2 + 1];
            float4 b4 = *(const float4*)&Bs[kk * 68 + tx * 4];
            acc[0][0] = fmaf(a0, b4.x, acc[0][0]); acc[0][1] = fmaf(a0, b4.y, acc[0][1]);
            acc[0][2] = fmaf(a0, b4.z, acc[0][2]); acc[0][3] = fmaf(a0, b4.w, acc[0][3]);
            acc[1][0] = fmaf(a1, b4.x, acc[1][0]); acc[1][1] = fmaf(a1, b4.y, acc[1][1]);
            acc[1][2] = fmaf(a1, b4.z, acc[1][2]); acc[1][3] = fmaf(a1, b4.w, acc[1][3]);
        }
        __syncthreads();
    }
#pragma unroll
    for (int mi = 0; mi < 2; mi++) {
        int gm = row0 + ty * 2 + mi;
        if (gm < NREL) {
#pragma unroll
            for (int ni = 0; ni < 4; ni++) {
                int gn = col0 + tx * 4 + ni;
                if (gn < M1) g_KrelT[gn * NRELP + gm] = acc[mi][ni] + fc1b[gn];
            }
        }
    }
}

// ======== KV: fold partials, scale, shift-replicate (+ scal0 block) =====
__global__ void __launch_bounds__(256) kv_build(
        const float* __restrict__ bn1g, const float* __restrict__ bn1b,
        const float* __restrict__ bn1m, const float* __restrict__ bn1v,
        const float* __restrict__ bn2g, const float* __restrict__ bn2b,
        const float* __restrict__ bn2m, const float* __restrict__ bn2v,
        const float* __restrict__ fc2w, const float* __restrict__ fc2b,
        const float* __restrict__ fcb) {
    __shared__ float sv[WOUT];
    __shared__ float red[256];
    int tid = threadIdx.x;
    if (blockIdx.x == OC) {                // scal0
        float t = 0.f;
        for (int i = tid; i < WIN; i += 256) {
            float s2 = bn2g[i] * rsqrtf(bn2v[i] + EPSBN);
            float a  = s2 * fc2w[i];
            t += (bn2b[i] - bn2m[i] * s2) * fc2w[i] + a * fcb[i];
        }
        red[tid] = t;
        __syncthreads();
        for (int s = 128; s; s >>= 1) { if (tid < s) red[tid] += red[tid + s]; __syncthreads(); }
        if (tid == 0) g_scal0 = red[0] + fc2b[0];
        return;
    }
    int o = blockIdx.x;
    float inv1 = bn1g[o] * rsqrtf(bn1v[o] + EPSBN);
    float vsum = 0.f;
    for (int w = tid; w < WOUT; w += 256) {
        float s = 0.f;
#pragma unroll
        for (int sp = 0; sp < NSPLIT; sp++) s += g_vp[sp * FCLEN + o * WOUT + w];
        sv[w] = s * inv1;
        vsum += s;
    }
    red[tid] = vsum;
    __syncthreads();
    for (int s = 128; s; s >>= 1) { if (tid < s) red[tid] += red[tid + s]; __syncthreads(); }
    if (tid == 0) g_c1[o] = (bn1b[o] - bn1m[o] * inv1) * red[0];
    __syncthreads();
    for (int idx = tid; idx < FW * WIN; idx += 256) {
        int j = idx / WIN, t = idx - j * WIN;
        int w = t - j;
        g_Vmat[(o * FW + j) * VPAD + t] = ((unsigned)w < (unsigned)WOUT) ? sv[w] : 0.f;
    }
}

// ======== GEMM2 v6: 32rel x 64t x 24k, 4x4 reg tile, 1344 blocks ========
__global__ void __launch_bounds__(128) gemm2_q() {
    __shared__ float sK[KLEN][RT];         // [kk][rel]
    __shared__ float sV[KLEN][TT];         // [kk][t]
    int tid = threadIdx.x;
    int tx = tid & 15;                     // t group  (x4)
    int ty = tid >> 4;                     // rel group (x4)
    int r0 = blockIdx.x * RT;
    int t0 = blockIdx.y * TT;
    int k0 = blockIdx.z * KLEN;

    // stage Krel chunk: 24x32 = 192 f4
    for (int i = tid; i < KLEN * (RT / 4); i += 128) {
        int kk = i >> 3, c = i & 7;
        *(float4*)&sK[kk][c * 4] =
            *(const float4*)&g_KrelT[(size_t)(k0 + kk) * NRELP + r0 + c * 4];
    }
    // stage Vmat chunk: 24x64 = 384 f4
    for (int i = tid; i < KLEN * (TT / 4); i += 128) {
        int kk = i >> 4, c = i & 15;
        *(float4*)&sV[kk][c * 4] =
            *(const float4*)&g_Vmat[(size_t)(k0 + kk) * VPAD + t0 + c * 4];
    }
    __syncthreads();

    float acc[4][4] = {};
#pragma unroll
    for (int kk = 0; kk < KLEN; kk++) {
        float4 a4 = *(const float4*)&sK[kk][ty * 4];
        float4 b4 = *(const float4*)&sV[kk][tx * 4];
        acc[0][0] = fmaf(a4.x, b4.x, acc[0][0]); acc[0][1] = fmaf(a4.x, b4.y, acc[0][1]);
        acc[0][2] = fmaf(a4.x, b4.z, acc[0][2]); acc[0][3] = fmaf(a4.x, b4.w, acc[0][3]);
        acc[1][0] = fmaf(a4.y, b4.x, acc[1][0]); acc[1][1] = fmaf(a4.y, b4.y, acc[1][1]);
        acc[1][2] = fmaf(a4.y, b4.z, acc[1][2]); acc[1][3] = fmaf(a4.y, b4.w, acc[1][3]);
        acc[2][0] = fmaf(a4.z, b4.x, acc[2][0]); acc[2][1] = fmaf(a4.z, b4.y, acc[2][1]);
        acc[2][2] = fmaf(a4.z, b4.z, acc[2][2]); acc[2][3] = fmaf(a4.z, b4.w, acc[2][3]);
        acc[3][0] = fmaf(a4.w, b4.x, acc[3][0]); acc[3][1] = fmaf(a4.w, b4.y, acc[3][1]);
        acc[3][2] = fmaf(a4.w, b4.z, acc[3][2]); acc[3][3] = fmaf(a4.w, b4.w, acc[3][3]);
    }

    float* __restrict__ qp = g_qp + (size_t)blockIdx.z * (NREL * WIN);
    int gn = t0 + tx * 4;
    if (gn < WIN) {
#pragma unroll
        for (int mi = 0; mi < 4; mi++) {
            int gm = r0 + ty * 4 + mi;
            if (gm < NREL) {
                float4 v = make_float4(acc[mi][0], acc[mi][1], acc[mi][2], acc[mi][3]);
                *(float4*)&qp[gm * WIN + gn] = v;
            }
        }
    }
}

// ======== FOLD: q = sum of 12 K-split partials ==========================
__global__ void __launch_bounds__(256) fold_q() {
    int idx = blockIdx.x * 256 + threadIdx.x;       // f4 index
    if (idx >= NREL * WIN / 4) return;
    float4 s = make_float4(0.f, 0.f, 0.f, 0.f);
#pragma unroll
    for (int p = 0; p < KSPL; p++) {
        float4 t = ((const float4*)(g_qp + (size_t)p * (NREL * WIN)))[idx];
        s.x += t.x; s.y += t.y; s.z += t.z; s.w += t.w;
    }
    ((float4*)g_q)[idx] = s;
}

// ======== K4: 2 warps per example ======================================
__global__ void __launch_bounds__(256) k4_main(
        const int* __restrict__ e1i, const int* __restrict__ ri,
        const int* __restrict__ e2i, const float* __restrict__ Et,
        const float* __restrict__ bn0g, const float* __restrict__ bn0b,
        const float* __restrict__ bn0m, const float* __restrict__ bn0v,
        const float* __restrict__ bias, float* __restrict__ out) {
    __shared__ float part[8];
    int tid = threadIdx.x;
    int lane = tid & 31;
    int half = (tid >> 5) & 1;
    int k = tid >> 6;
    int b = blockIdx.x * 4 + k;
    float s0 = bn0g[0] * rsqrtf(bn0v[0] + EPSBN);
    float c0 = bn0b[0] - bn0m[0] * s0;
    int r  = ri[b];
    int e  = half ? e2i[b] : e1i[b];
    const float4* __restrict__ E = (const float4*)(Et + (size_t)e * D1);
    const float4* __restrict__ Q = (const float4*)(g_q + r * WIN) + half * 50;
    float acc = half ? 0.f : g_c1[lane];
    {
        float4 ev = E[lane], qv = Q[lane];
        acc = fmaf(fmaf(s0, ev.x, c0), qv.x, acc);
        acc = fmaf(fmaf(s0, ev.y, c0), qv.y, acc);
        acc = fmaf(fmaf(s0, ev.z, c0), qv.z, acc);
        acc = fmaf(fmaf(s0, ev.w, c0), qv.w, acc);
    }
    if (lane < 18) {
        float4 ev = E[lane + 32], qv = Q[lane + 32];
        acc = fmaf(fmaf(s0, ev.x, c0), qv.x, acc);
        acc = fmaf(fmaf(s0, ev.y, c0), qv.y, acc);
        acc = fmaf(fmaf(s0, ev.z, c0), qv.z, acc);
        acc = fmaf(fmaf(s0, ev.w, c0), qv.w, acc);
    }
    for (int o = 16; o; o >>= 1) acc += __shfl_down_sync(0xffffffffu, acc, o);
    if (lane == 0) part[tid >> 5] = acc;
    __syncthreads();
    if ((tid & 63) == 0) {
        int w = tid >> 5;
        float z = part[w] + part[w + 1] + g_scal0;
        out[b] = tanhf(z) + bias[0];
    }
}

// ---------------- launch ------------------------------------------------
extern "C" void kernel_launch(void* const* d_in, const int* in_sizes, int n_in,
                              void* d_out, int out_size) {
    const int*   e1_idx  = (const int*)  d_in[0];
    const int*   r_idx   = (const int*)  d_in[1];
    const int*   e2_idx  = (const int*)  d_in[2];
    const float* E_table = (const float*)d_in[3];
    const float* R_table = (const float*)d_in[4];
    const float* bn0g    = (const float*)d_in[5];
    const float* bn0b    = (const float*)d_in[6];
    const float* bn0m    = (const float*)d_in[7];
    const float* bn0v    = (const float*)d_in[8];
    const float* fc1w    = (const float*)d_in[9];
    const float* fc1b    = (const float*)d_in[10];
    const float* bn1g    = (const float*)d_in[11];
    const float* bn1b    = (const float*)d_in[12];
    const float* bn1m    = (const float*)d_in[13];
    const float* bn1v    = (const float*)d_in[14];
    const float* fcw     = (const float*)d_in[15];
    const float* fcb     = (const float*)d_in[16];
    const float* bn2g    = (const float*)d_in[17];
    const float* bn2b    = (const float*)d_in[18];
    const float* bn2m    = (const float*)d_in[19];
    const float* bn2v    = (const float*)d_in[20];
    const float* fc2w    = (const float*)d_in[21];
    const float* fc2b    = (const float*)d_in[22];
    const float* bias    = (const float*)d_in[23];
    float* out = (float*)d_out;

    k1_v<<<NSPLIT * FBLK, 256>>>(fcw, bn2g, bn2v, fc2w);
    gemm1_krel<<<dim3(G1_ROWB, G1_COLB), 256>>>(R_table, fc1w, fc1b);
    kv_build<<<OC + 1, 256>>>(bn1g, bn1b, bn1m, bn1v,
                              bn2g, bn2b, bn2m, bn2v, fc2w, fc2b, fcb);
    gemm2_q<<<dim3(RTILES, TTILES, KSPL), 128>>>();
    fold_q<<<(NREL * WIN / 4 + 255) / 256, 256>>>();
    k4_main<<<BATCH / 4, 256>>>(e1_idx, r_idx, e2_idx, E_table,
                                bn0g, bn0b, bn0m, bn0v, bias, out);
}

// round 9
// speedup vs baseline: 1.1513x; 1.1513x over previous
#include <cuda_runtime.h>
#include <cuda_bf16.h>
#include <math.h>

#define BATCH   4096
#define D1      200
#define NREL    500
#define NRELP   512
#define M1      288
#define OC      32
#define FW      9
#define WOUT    392
#define WIN     400
#define VPAD    512
#define FCLEN   12544
#define EPSBN   1e-5f
#define NSPLIT  16
#define ILEN    25       // WIN / NSPLIT
#define FBLK    49

// gemm1 v2 geometry: Krel partials, 32rel x 64m, K-split 4 (KC=50)
#define G1_RT   32
#define G1_MT   64
#define G1_KC   50
#define G1_KSPL 4

// gemm2 v7 geometry
#define RT      32       // rel tile
#define TT      128      // t tile
#define KSPL    12
#define KLEN    24       // 288/12
#define RTILES  16       // 512/32
#define TTILES  4        // 512/128

// ---------------- device scratch ----------------
__device__ float g_vp[NSPLIT * FCLEN];
__device__ float g_kp[G1_KSPL * M1 * NRELP];  // gemm1 K-split partials
__device__ float g_Vmat[M1 * VPAD];           // pad cols stay zero
__device__ float g_qp[KSPL * NREL * WIN];     // gemm2 K-split partials
__device__ float g_q[NREL * WIN];
__device__ float g_c1[OC];
__device__ float g_scal0;

// ======== K1: v partials (16-way i-split) ===============================
__global__ void __launch_bounds__(256) k1_v(
        const float* __restrict__ fcw,
        const float* __restrict__ bn2g, const float* __restrict__ bn2v,
        const float* __restrict__ fc2w) {
    __shared__ float sa[ILEN];
    int tid = threadIdx.x;
    int isp = blockIdx.x / FBLK, fb = blockIdx.x % FBLK;
    if (tid < ILEN) {
        int i = isp * ILEN + tid;
        float s2 = bn2g[i] * rsqrtf(bn2v[i] + EPSBN);
        sa[tid] = s2 * fc2w[i];
    }
    __syncthreads();
    int f = fb * 256 + tid;
    const float* __restrict__ p = fcw + (size_t)isp * ILEN * FCLEN + f;
    float acc = 0.f;
#pragma unroll
    for (int ii = 0; ii < ILEN; ii++)
        acc = fmaf(sa[ii], p[(size_t)ii * FCLEN], acc);
    g_vp[isp * FCLEN + f] = acc;
}

// ======== GEMM1 v2: Krel partials = R @ fc1w^T (K-split 4) ==============
__global__ void __launch_bounds__(256) gemm1_krel(
        const float* __restrict__ R, const float* __restrict__ fc1w) {
    __shared__ float sR[G1_KC][G1_RT + 4];   // pad 36 (f2-aligned)
    __shared__ float sW[G1_KC][G1_MT + 4];   // pad 68 (f4-aligned)
    int tid = threadIdx.x;
    int r0 = blockIdx.x * G1_RT;
    int m0 = blockIdx.y * G1_MT;
    int k0 = blockIdx.z * G1_KC;

    // stage R chunk: reads coalesced along k (rel-major index)
    for (int i = tid; i < G1_RT * G1_KC; i += 256) {
        int rel = i / G1_KC, kk = i - rel * G1_KC;
        int gr = r0 + rel;
        sR[kk][rel] = (gr < NREL) ? R[gr * 200 + k0 + kk] : 0.f;
    }
    // stage fc1w chunk
    for (int i = tid; i < G1_MT * G1_KC; i += 256) {
        int m = i / G1_KC, kk = i - m * G1_KC;
        int gm = m0 + m;
        sW[kk][m] = (gm < M1) ? fc1w[gm * 200 + k0 + kk] : 0.f;
    }
    __syncthreads();

    int tx = tid & 15;                 // rel group (x2)
    int ty = tid >> 4;                 // m group (x4)
    float acc[2][4] = {};
#pragma unroll 5
    for (int kk = 0; kk < G1_KC; kk++) {
        float2 a2 = *(const float2*)&sR[kk][tx * 2];
        float4 b4 = *(const float4*)&sW[kk][ty * 4];
        acc[0][0] = fmaf(a2.x, b4.x, acc[0][0]); acc[0][1] = fmaf(a2.x, b4.y, acc[0][1]);
        acc[0][2] = fmaf(a2.x, b4.z, acc[0][2]); acc[0][3] = fmaf(a2.x, b4.w, acc[0][3]);
        acc[1][0] = fmaf(a2.y, b4.x, acc[1][0]); acc[1][1] = fmaf(a2.y, b4.y, acc[1][1]);
        acc[1][2] = fmaf(a2.y, b4.z, acc[1][2]); acc[1][3] = fmaf(a2.y, b4.w, acc[1][3]);
    }
    float* __restrict__ kp = g_kp + (size_t)blockIdx.z * (M1 * NRELP);
#pragma unroll
    for (int j = 0; j < 4; j++) {
        int gm = m0 + ty * 4 + j;
        if (gm < M1) {
            float2 v = make_float2(acc[0][j], acc[1][j]);
            *(float2*)&kp[gm * NRELP + r0 + tx * 2] = v;
        }
    }
}

// ======== KV: fold partials, scale, shift-replicate (+ scal0 block) =====
__global__ void __launch_bounds__(256) kv_build(
        const float* __restrict__ bn1g, const float* __restrict__ bn1b,
        const float* __restrict__ bn1m, const float* __restrict__ bn1v,
        const float* __restrict__ bn2g, const float* __restrict__ bn2b,
        const float* __restrict__ bn2m, const float* __restrict__ bn2v,
        const float* __restrict__ fc2w, const float* __restrict__ fc2b,
        const float* __restrict__ fcb) {
    __shared__ float sv[WOUT];
    __shared__ float red[256];
    int tid = threadIdx.x;
    if (blockIdx.x == OC) {                // scal0
        float t = 0.f;
        for (int i = tid; i < WIN; i += 256) {
            float s2 = bn2g[i] * rsqrtf(bn2v[i] + EPSBN);
            float a  = s2 * fc2w[i];
            t += (bn2b[i] - bn2m[i] * s2) * fc2w[i] + a * fcb[i];
        }
        red[tid] = t;
        __syncthreads();
        for (int s = 128; s; s >>= 1) { if (tid < s) red[tid] += red[tid + s]; __syncthreads(); }
        if (tid == 0) g_scal0 = red[0] + fc2b[0];
        return;
    }
    int o = blockIdx.x;
    float inv1 = bn1g[o] * rsqrtf(bn1v[o] + EPSBN);
    float vsum = 0.f;
    for (int w = tid; w < WOUT; w += 256) {
        float s = 0.f;
#pragma unroll
        for (int sp = 0; sp < NSPLIT; sp++) s += g_vp[sp * FCLEN + o * WOUT + w];
        sv[w] = s * inv1;
        vsum += s;
    }
    red[tid] = vsum;
    __syncthreads();
    for (int s = 128; s; s >>= 1) { if (tid < s) red[tid] += red[tid + s]; __syncthreads(); }
    if (tid == 0) g_c1[o] = (bn1b[o] - bn1m[o] * inv1) * red[0];
    __syncthreads();
    for (int idx = tid; idx < FW * WIN; idx += 256) {
        int j = idx / WIN, t = idx - j * WIN;
        int w = t - j;
        g_Vmat[(o * FW + j) * VPAD + t] = ((unsigned)w < (unsigned)WOUT) ? sv[w] : 0.f;
    }
}

// ======== GEMM2 v7: 32rel x 128t x 24k, 256 thr, folds gemm1 partials ===
__global__ void __launch_bounds__(256) gemm2_q(const float* __restrict__ fc1b) {
    __shared__ float sK[KLEN][RT];         // [kk][rel] (Krel = sum kp + bias)
    __shared__ float sV[KLEN][TT];         // [kk][t]
    int tid = threadIdx.x;
    int tx = tid & 31;                     // t group  (x4)
    int ty = tid >> 5;                     // rel group (x4)
    int r0 = blockIdx.x * RT;
    int t0 = blockIdx.y * TT;
    int k0 = blockIdx.z * KLEN;

    // stage Krel chunk: fold 4 gemm1 partials + bias
    for (int i = tid; i < KLEN * RT; i += 256) {
        int kk = i >> 5, rel = i & 31;
        size_t off = (size_t)(k0 + kk) * NRELP + r0 + rel;
        float s = fc1b[k0 + kk];
#pragma unroll
        for (int z = 0; z < G1_KSPL; z++)
            s += g_kp[(size_t)z * (M1 * NRELP) + off];
        sK[kk][rel] = s;
    }
    // stage Vmat chunk: 24x128 = 768 f4
    for (int i = tid; i < KLEN * (TT / 4); i += 256) {
        int kk = i >> 5, c = i & 31;
        *(float4*)&sV[kk][c * 4] =
            *(const float4*)&g_Vmat[(size_t)(k0 + kk) * VPAD + t0 + c * 4];
    }
    __syncthreads();

    float acc[4][4] = {};
#pragma unroll
    for (int kk = 0; kk < KLEN; kk++) {
        float4 a4 = *(const float4*)&sK[kk][ty * 4];
        float4 b4 = *(const float4*)&sV[kk][tx * 4];
        acc[0][0] = fmaf(a4.x, b4.x, acc[0][0]); acc[0][1] = fmaf(a4.x, b4.y, acc[0][1]);
        acc[0][2] = fmaf(a4.x, b4.z, acc[0][2]); acc[0][3] = fmaf(a4.x, b4.w, acc[0][3]);
        acc[1][0] = fmaf(a4.y, b4.x, acc[1][0]); acc[1][1] = fmaf(a4.y, b4.y, acc[1][1]);
        acc[1][2] = fmaf(a4.y, b4.z, acc[1][2]); acc[1][3] = fmaf(a4.y, b4.w, acc[1][3]);
        acc[2][0] = fmaf(a4.z, b4.x, acc[2][0]); acc[2][1] = fmaf(a4.z, b4.y, acc[2][1]);
        acc[2][2] = fmaf(a4.z, b4.z, acc[2][2]); acc[2][3] = fmaf(a4.z, b4.w, acc[2][3]);
        acc[3][0] = fmaf(a4.w, b4.x, acc[3][0]); acc[3][1] = fmaf(a4.w, b4.y, acc[3][1]);
        acc[3][2] = fmaf(a4.w, b4.z, acc[3][2]); acc[3][3] = fmaf(a4.w, b4.w, acc[3][3]);
    }

    float* __restrict__ qp = g_qp + (size_t)blockIdx.z * (NREL * WIN);
    int gn = t0 + tx * 4;
    if (gn < WIN) {
#pragma unroll
        for (int mi = 0; mi < 4; mi++) {
            int gm = r0 + ty * 4 + mi;
            if (gm < NREL) {
                float4 v = make_float4(acc[mi][0], acc[mi][1], acc[mi][2], acc[mi][3]);
                *(float4*)&qp[gm * WIN + gn] = v;
            }
        }
    }
}

// ======== FOLD: q = sum of 12 K-split partials ==========================
__global__ void __launch_bounds__(256) fold_q() {
    int idx = blockIdx.x * 256 + threadIdx.x;       // f4 index
    if (idx >= NREL * WIN / 4) return;
    float4 s = make_float4(0.f, 0.f, 0.f, 0.f);
#pragma unroll
    for (int p = 0; p < KSPL; p++) {
        float4 t = ((const float4*)(g_qp + (size_t)p * (NREL * WIN)))[idx];
        s.x += t.x; s.y += t.y; s.z += t.z; s.w += t.w;
    }
    ((float4*)g_q)[idx] = s;
}

// ======== K4: 2 warps per example ======================================
__global__ void __launch_bounds__(256) k4_main(
        const int* __restrict__ e1i, const int* __restrict__ ri,
        const int* __restrict__ e2i, const float* __restrict__ Et,
        const float* __restrict__ bn0g, const float* __restrict__ bn0b,
        const float* __restrict__ bn0m, const float* __restrict__ bn0v,
        const float* __restrict__ bias, float* __restrict__ out) {
    __shared__ float part[8];
    int tid = threadIdx.x;
    int lane = tid & 31;
    int half = (tid >> 5) & 1;
    int k = tid >> 6;
    int b = blockIdx.x * 4 + k;
    float s0 = bn0g[0] * rsqrtf(bn0v[0] + EPSBN);
    float c0 = bn0b[0] - bn0m[0] * s0;
    int r  = ri[b];
    int e  = half ? e2i[b] : e1i[b];
    const float4* __restrict__ E = (const float4*)(Et + (size_t)e * D1);
    const float4* __restrict__ Q = (const float4*)(g_q + r * WIN) + half * 50;
    float acc = half ? 0.f : g_c1[lane];
    {
        float4 ev = E[lane], qv = Q[lane];
        acc = fmaf(fmaf(s0, ev.x, c0), qv.x, acc);
        acc = fmaf(fmaf(s0, ev.y, c0), qv.y, acc);
        acc = fmaf(fmaf(s0, ev.z, c0), qv.z, acc);
        acc = fmaf(fmaf(s0, ev.w, c0), qv.w, acc);
    }
    if (lane < 18) {
        float4 ev = E[lane + 32], qv = Q[lane + 32];
        acc = fmaf(fmaf(s0, ev.x, c0), qv.x, acc);
        acc = fmaf(fmaf(s0, ev.y, c0), qv.y, acc);
        acc = fmaf(fmaf(s0, ev.z, c0), qv.z, acc);
        acc = fmaf(fmaf(s0, ev.w, c0), qv.w, acc);
    }
    for (int o = 16; o; o >>= 1) acc += __shfl_down_sync(0xffffffffu, acc, o);
    if (lane == 0) part[tid >> 5] = acc;
    __syncthreads();
    if ((tid & 63) == 0) {
        int w = tid >> 5;
        float z = part[w] + part[w + 1] + g_scal0;
        out[b] = tanhf(z) + bias[0];
    }
}

// ---------------- launch ------------------------------------------------
extern "C" void kernel_launch(void* const* d_in, const int* in_sizes, int n_in,
                              void* d_out, int out_size) {
    const int*   e1_idx  = (const int*)  d_in[0];
    const int*   r_idx   = (const int*)  d_in[1];
    const int*   e2_idx  = (const int*)  d_in[2];
    const float* E_table = (const float*)d_in[3];
    const float* R_table = (const float*)d_in[4];
    const float* bn0g    = (const float*)d_in[5];
    const float* bn0b    = (const float*)d_in[6];
    const float* bn0m    = (const float*)d_in[7];
    const float* bn0v    = (const float*)d_in[8];
    const float* fc1w    = (const float*)d_in[9];
    const float* fc1b    = (const float*)d_in[10];
    const float* bn1g    = (const float*)d_in[11];
    const float* bn1b    = (const float*)d_in[12];
    const float* bn1m    = (const float*)d_in[13];
    const float* bn1v    = (const float*)d_in[14];
    const float* fcw     = (const float*)d_in[15];
    const float* fcb     = (const float*)d_in[16];
    const float* bn2g    = (const float*)d_in[17];
    const float* bn2b    = (const float*)d_in[18];
    const float* bn2m    = (const float*)d_in[19];
    const float* bn2v    = (const float*)d_in[20];
    const float* fc2w    = (const float*)d_in[21];
    const float* fc2b    = (const float*)d_in[22];
    const float* bias    = (const float*)d_in[23];
    float* out = (float*)d_out;

    k1_v<<<NSPLIT * FBLK, 256>>>(fcw, bn2g, bn2v, fc2w);
    gemm1_krel<<<dim3(16, 5, G1_KSPL), 256>>>(R_table, fc1w);
    kv_build<<<OC + 1, 256>>>(bn1g, bn1b, bn1m, bn1v,
                              bn2g, bn2b, bn2m, bn2v, fc2w, fc2b, fcb);
    gemm2_q<<<dim3(RTILES, TTILES, KSPL), 256>>>(fc1b);
    fold_q<<<(NREL * WIN / 4 + 255) / 256, 256>>>();
    k4_main<<<BATCH / 4, 256>>>(e1_idx, r_idx, e2_idx, E_table,
                                bn0g, bn0b, bn0m, bn0v, bias, out);
}

// round 10
// speedup vs baseline: 1.2089x; 1.0501x over previous
#include <cuda_runtime.h>
#include <cuda_bf16.h>
#include <math.h>

#define BATCH   4096
#define D1      200
#define NREL    500
#define NRELP   512
#define M1      288
#define OC      32
#define FW      9
#define WOUT    392
#define WIN     400
#define VPAD    512
#define FCLEN   12544
#define EPSBN   1e-5f
#define NSPLIT  16
#define ILEN    25       // WIN / NSPLIT
#define FBLK    49

// gemm1 v2 geometry
#define G1_RT   32
#define G1_MT   64
#define G1_KC   50
#define G1_KSPL 4

// gemm2 v8 geometry
#define RT      32       // rel tile
#define TT      64       // t tile
#define KSPL    12
#define KLEN    24       // 288/12
#define RTILES  16       // 512/32
#define TTILES  7        // ceil(400/64) -> covers 448

typedef unsigned long long ull;

__device__ __forceinline__ void ffma2(ull &d, ull a, ull b) {
    asm("fma.rn.f32x2 %0, %1, %2, %0;" : "+l"(d) : "l"(a), "l"(b));
}
__device__ __forceinline__ ull dup2(float x) {
    ull r; asm("mov.b64 %0, {%1, %1};" : "=l"(r) : "f"(x)); return r;
}
__device__ __forceinline__ void unpack2(float &lo, float &hi, ull v) {
    asm("mov.b64 {%0, %1}, %2;" : "=f"(lo), "=f"(hi) : "l"(v));
}

// ---------------- device scratch ----------------
__device__ float g_vp[NSPLIT * FCLEN];
__device__ float g_kp[G1_KSPL * M1 * NRELP];  // gemm1 K-split partials
__device__ float g_Vmat[M1 * VPAD];           // pad cols stay zero
__device__ float g_qp[KSPL * NREL * WIN];     // gemm2 K-split partials
__device__ float g_q[NREL * WIN];
__device__ float g_c1[OC];
__device__ float g_scal0;

// ======== K1: v partials (16-way i-split) ===============================
__global__ void __launch_bounds__(256) k1_v(
        const float* __restrict__ fcw,
        const float* __restrict__ bn2g, const float* __restrict__ bn2v,
        const float* __restrict__ fc2w) {
    __shared__ float sa[ILEN];
    int tid = threadIdx.x;
    int isp = blockIdx.x / FBLK, fb = blockIdx.x % FBLK;
    if (tid < ILEN) {
        int i = isp * ILEN + tid;
        float s2 = bn2g[i] * rsqrtf(bn2v[i] + EPSBN);
        sa[tid] = s2 * fc2w[i];
    }
    __syncthreads();
    int f = fb * 256 + tid;
    const float* __restrict__ p = fcw + (size_t)isp * ILEN * FCLEN + f;
    float acc = 0.f;
#pragma unroll
    for (int ii = 0; ii < ILEN; ii++)
        acc = fmaf(sa[ii], p[(size_t)ii * FCLEN], acc);
    g_vp[isp * FCLEN + f] = acc;
}

// ======== GEMM1 v2: Krel partials = R @ fc1w^T (K-split 4) ==============
__global__ void __launch_bounds__(256) gemm1_krel(
        const float* __restrict__ R, const float* __restrict__ fc1w) {
    __shared__ float sR[G1_KC][G1_RT + 4];
    __shared__ float sW[G1_KC][G1_MT + 4];
    int tid = threadIdx.x;
    int r0 = blockIdx.x * G1_RT;
    int m0 = blockIdx.y * G1_MT;
    int k0 = blockIdx.z * G1_KC;

    for (int i = tid; i < G1_RT * G1_KC; i += 256) {
        int rel = i / G1_KC, kk = i - rel * G1_KC;
        int gr = r0 + rel;
        sR[kk][rel] = (gr < NREL) ? R[gr * 200 + k0 + kk] : 0.f;
    }
    for (int i = tid; i < G1_MT * G1_KC; i += 256) {
        int m = i / G1_KC, kk = i - m * G1_KC;
        int gm = m0 + m;
        sW[kk][m] = (gm < M1) ? fc1w[gm * 200 + k0 + kk] : 0.f;
    }
    __syncthreads();

    int tx = tid & 15;                 // rel group (x2)
    int ty = tid >> 4;                 // m group (x4)
    float acc[2][4] = {};
#pragma unroll 5
    for (int kk = 0; kk < G1_KC; kk++) {
        float2 a2 = *(const float2*)&sR[kk][tx * 2];
        float4 b4 = *(const float4*)&sW[kk][ty * 4];
        acc[0][0] = fmaf(a2.x, b4.x, acc[0][0]); acc[0][1] = fmaf(a2.x, b4.y, acc[0][1]);
        acc[0][2] = fmaf(a2.x, b4.z, acc[0][2]); acc[0][3] = fmaf(a2.x, b4.w, acc[0][3]);
        acc[1][0] = fmaf(a2.y, b4.x, acc[1][0]); acc[1][1] = fmaf(a2.y, b4.y, acc[1][1]);
        acc[1][2] = fmaf(a2.y, b4.z, acc[1][2]); acc[1][3] = fmaf(a2.y, b4.w, acc[1][3]);
    }
    float* __restrict__ kp = g_kp + (size_t)blockIdx.z * (M1 * NRELP);
#pragma unroll
    for (int j = 0; j < 4; j++) {
        int gm = m0 + ty * 4 + j;
        if (gm < M1) {
            float2 v = make_float2(acc[0][j], acc[1][j]);
            *(float2*)&kp[gm * NRELP + r0 + tx * 2] = v;
        }
    }
}

// ======== KV: fold partials, scale, shift-replicate (+ scal0 block) =====
__global__ void __launch_bounds__(256) kv_build(
        const float* __restrict__ bn1g, const float* __restrict__ bn1b,
        const float* __restrict__ bn1m, const float* __restrict__ bn1v,
        const float* __restrict__ bn2g, const float* __restrict__ bn2b,
        const float* __restrict__ bn2m, const float* __restrict__ bn2v,
        const float* __restrict__ fc2w, const float* __restrict__ fc2b,
        const float* __restrict__ fcb) {
    __shared__ float sv[WOUT];
    __shared__ float red[256];
    int tid = threadIdx.x;
    if (blockIdx.x == OC) {                // scal0
        float t = 0.f;
        for (int i = tid; i < WIN; i += 256) {
            float s2 = bn2g[i] * rsqrtf(bn2v[i] + EPSBN);
            float a  = s2 * fc2w[i];
            t += (bn2b[i] - bn2m[i] * s2) * fc2w[i] + a * fcb[i];
        }
        red[tid] = t;
        __syncthreads();
        for (int s = 128; s; s >>= 1) { if (tid < s) red[tid] += red[tid + s]; __syncthreads(); }
        if (tid == 0) g_scal0 = red[0] + fc2b[0];
        return;
    }
    int o = blockIdx.x;
    float inv1 = bn1g[o] * rsqrtf(bn1v[o] + EPSBN);
    float vsum = 0.f;
    for (int w = tid; w < WOUT; w += 256) {
        float s = 0.f;
#pragma unroll
        for (int sp = 0; sp < NSPLIT; sp++) s += g_vp[sp * FCLEN + o * WOUT + w];
        sv[w] = s * inv1;
        vsum += s;
    }
    red[tid] = vsum;
    __syncthreads();
    for (int s = 128; s; s >>= 1) { if (tid < s) red[tid] += red[tid + s]; __syncthreads(); }
    if (tid == 0) g_c1[o] = (bn1b[o] - bn1m[o] * inv1) * red[0];
    __syncthreads();
    for (int idx = tid; idx < FW * WIN; idx += 256) {
        int j = idx / WIN, t = idx - j * WIN;
        int w = t - j;
        g_Vmat[(o * FW + j) * VPAD + t] = ((unsigned)w < (unsigned)WOUT) ? sv[w] : 0.f;
    }
}

// ======== GEMM2 v8: 32rel x 64t x 24k, FFMA2, f4-fold staging ===========
__global__ void __launch_bounds__(128) gemm2_q(const float* __restrict__ fc1b) {
    __shared__ float sK[KLEN][RT];         // Krel = sum kp planes + bias
    __shared__ float sV[KLEN][TT];
    int tid = threadIdx.x;
    int tx = tid & 15;                     // t group  (x4): 0..15
    int ty = tid >> 4;                     // rel group (x4): 0..7
    int r0 = blockIdx.x * RT;
    int t0 = blockIdx.y * TT;
    int k0 = blockIdx.z * KLEN;

    // stage Krel chunk: 24x32 = 192 f4 over 4 planes + bias
    for (int i = tid; i < KLEN * (RT / 4); i += 128) {
        int kk = i >> 3, c = i & 7;
        size_t off = (size_t)(k0 + kk) * NRELP + r0 + c * 4;
        float4 s0 = *(const float4*)&g_kp[off];
        float4 s1 = *(const float4*)&g_kp[(size_t)1 * (M1 * NRELP) + off];
        float4 s2 = *(const float4*)&g_kp[(size_t)2 * (M1 * NRELP) + off];
        float4 s3 = *(const float4*)&g_kp[(size_t)3 * (M1 * NRELP) + off];
        float b = fc1b[k0 + kk];
        float4 s = make_float4(s0.x + s1.x + s2.x + s3.x + b,
                               s0.y + s1.y + s2.y + s3.y + b,
                               s0.z + s1.z + s2.z + s3.z + b,
                               s0.w + s1.w + s2.w + s3.w + b);
        *(float4*)&sK[kk][c * 4] = s;
    }
    // stage Vmat chunk: 24x64 = 384 f4
    for (int i = tid; i < KLEN * (TT / 4); i += 128) {
        int kk = i >> 4, c = i & 15;
        *(float4*)&sV[kk][c * 4] =
            *(const float4*)&g_Vmat[(size_t)(k0 + kk) * VPAD + t0 + c * 4];
    }
    __syncthreads();

    // acc[p][n]: rel-pair p (2 rels packed f32x2) x t column n
    ull acc[2][4] = {};
#pragma unroll
    for (int kk = 0; kk < KLEN; kk++) {
        ull a01 = *(const ull*)&sK[kk][ty * 4];       // rels +0,+1
        ull a23 = *(const ull*)&sK[kk][ty * 4 + 2];   // rels +2,+3
        float4 b4 = *(const float4*)&sV[kk][tx * 4];
        ull bx = dup2(b4.x), by = dup2(b4.y), bz = dup2(b4.z), bw = dup2(b4.w);
        ffma2(acc[0][0], a01, bx); ffma2(acc[0][1], a01, by);
        ffma2(acc[0][2], a01, bz); ffma2(acc[0][3], a01, bw);
        ffma2(acc[1][0], a23, bx); ffma2(acc[1][1], a23, by);
        ffma2(acc[1][2], a23, bz); ffma2(acc[1][3], a23, bw);
    }

    // unpack to rel-major rows
    float r[4][4];
#pragma unroll
    for (int n = 0; n < 4; n++) {
        unpack2(r[0][n], r[1][n], acc[0][n]);
        unpack2(r[2][n], r[3][n], acc[1][n]);
    }

    float* __restrict__ qp = g_qp + (size_t)blockIdx.z * (NREL * WIN);
    int gn = t0 + tx * 4;
    if (gn < WIN) {
#pragma unroll
        for (int mi = 0; mi < 4; mi++) {
            int gm = r0 + ty * 4 + mi;
            if (gm < NREL) {
                float4 v = make_float4(r[mi][0], r[mi][1], r[mi][2], r[mi][3]);
                *(float4*)&qp[gm * WIN + gn] = v;
            }
        }
    }
}

// ======== FOLD: q = sum of 12 K-split partials ==========================
__global__ void __launch_bounds__(256) fold_q() {
    int idx = blockIdx.x * 256 + threadIdx.x;
    if (idx >= NREL * WIN / 4) return;
    float4 s = make_float4(0.f, 0.f, 0.f, 0.f);
#pragma unroll
    for (int p = 0; p < KSPL; p++) {
        float4 t = ((const float4*)(g_qp + (size_t)p * (NREL * WIN)))[idx];
        s.x += t.x; s.y += t.y; s.z += t.z; s.w += t.w;
    }
    ((float4*)g_q)[idx] = s;
}

// ======== K4: 2 warps per example ======================================
__global__ void __launch_bounds__(256) k4_main(
        const int* __restrict__ e1i, const int* __restrict__ ri,
        const int* __restrict__ e2i, const float* __restrict__ Et,
        const float* __restrict__ bn0g, const float* __restrict__ bn0b,
        const float* __restrict__ bn0m, const float* __restrict__ bn0v,
        const float* __restrict__ bias, float* __restrict__ out) {
    __shared__ float part[8];
    int tid = threadIdx.x;
    int lane = tid & 31;
    int half = (tid >> 5) & 1;
    int k = tid >> 6;
    int b = blockIdx.x * 4 + k;
    float s0 = bn0g[0] * rsqrtf(bn0v[0] + EPSBN);
    float c0 = bn0b[0] - bn0m[0] * s0;
    int r  = ri[b];
    int e  = half ? e2i[b] : e1i[b];
    const float4* __restrict__ E = (const float4*)(Et + (size_t)e * D1);
    const float4* __restrict__ Q = (const float4*)(g_q + r * WIN) + half * 50;
    float acc = half ? 0.f : g_c1[lane];
    {
        float4 ev = E[lane], qv = Q[lane];
        acc = fmaf(fmaf(s0, ev.x, c0), qv.x, acc);
        acc = fmaf(fmaf(s0, ev.y, c0), qv.y, acc);
        acc = fmaf(fmaf(s0, ev.z, c0), qv.z, acc);
        acc = fmaf(fmaf(s0, ev.w, c0), qv.w, acc);
    }
    if (lane < 18) {
        float4 ev = E[lane + 32], qv = Q[lane + 32];
        acc = fmaf(fmaf(s0, ev.x, c0), qv.x, acc);
        acc = fmaf(fmaf(s0, ev.y, c0), qv.y, acc);
        acc = fmaf(fmaf(s0, ev.z, c0), qv.z, acc);
        acc = fmaf(fmaf(s0, ev.w, c0), qv.w, acc);
    }
    for (int o = 16; o; o >>= 1) acc += __shfl_down_sync(0xffffffffu, acc, o);
    if (lane == 0) part[tid >> 5] = acc;
    __syncthreads();
    if ((tid & 63) == 0) {
        int w = tid >> 5;
        float z = part[w] + part[w + 1] + g_scal0;
        out[b] = tanhf(z) + bias[0];
    }
}

// ---------------- launch ------------------------------------------------
extern "C" void kernel_launch(void* const* d_in, const int* in_sizes, int n_in,
                              void* d_out, int out_size) {
    const int*   e1_idx  = (const int*)  d_in[0];
    const int*   r_idx   = (const int*)  d_in[1];
    const int*   e2_idx  = (const int*)  d_in[2];
    const float* E_table = (const float*)d_in[3];
    const float* R_table = (const float*)d_in[4];
    const float* bn0g    = (const float*)d_in[5];
    const float* bn0b    = (const float*)d_in[6];
    const float* bn0m    = (const float*)d_in[7];
    const float* bn0v    = (const float*)d_in[8];
    const float* fc1w    = (const float*)d_in[9];
    const float* fc1b    = (const float*)d_in[10];
    const float* bn1g    = (const float*)d_in[11];
    const float* bn1b    = (const float*)d_in[12];
    const float* bn1m    = (const float*)d_in[13];
    const float* bn1v    = (const float*)d_in[14];
    const float* fcw     = (const float*)d_in[15];
    const float* fcb     = (const float*)d_in[16];
    const float* bn2g    = (const float*)d_in[17];
    const float* bn2b    = (const float*)d_in[18];
    const float* bn2m    = (const float*)d_in[19];
    const float* bn2v    = (const float*)d_in[20];
    const float* fc2w    = (const float*)d_in[21];
    const float* fc2b    = (const float*)d_in[22];
    const float* bias    = (const float*)d_in[23];
    float* out = (float*)d_out;

    k1_v<<<NSPLIT * FBLK, 256>>>(fcw, bn2g, bn2v, fc2w);
    gemm1_krel<<<dim3(16, 5, G1_KSPL), 256>>>(R_table, fc1w);
    kv_build<<<OC + 1, 256>>>(bn1g, bn1b, bn1m, bn1v,
                              bn2g, bn2b, bn2m, bn2v, fc2w, fc2b, fcb);
    gemm2_q<<<dim3(RTILES, TTILES, KSPL), 128>>>(fc1b);
    fold_q<<<(NREL * WIN / 4 + 255) / 256, 256>>>();
    k4_main<<<BATCH / 4, 256>>>(e1_idx, r_idx, e2_idx, E_table,
                                bn0g, bn0b, bn0m, bn0v, bias, out);
}

// round 11
// speedup vs baseline: 1.2413x; 1.0268x over previous
#include <cuda_runtime.h>
#include <cuda_bf16.h>
#include <math.h>

#define BATCH   4096
#define D1      200
#define NREL    500
#define NRELP   512
#define M1      288
#define OC      32
#define FW      9
#define WOUT    392
#define WIN     400
#define VPAD    512
#define FCLEN   12544
#define EPSBN   1e-5f
#define NSPLIT  16
#define ILEN    25
#define FBLK    49

#define DPADB   208      // gemmB contraction extent (200 R dims + 1 bias row + pad)
#define W2ROWS  224      // padded W2 row count (7 x 32 d-tiles)
#define W2PAD   512      // W2 row stride
#define KSPL_A  12
#define KLEN_A  24       // 288/12
#define KSPL_B  8
#define KLEN_B  26       // 208/8

typedef unsigned long long ull;

__device__ __forceinline__ void ffma2(ull &d, ull a, ull b) {
    asm("fma.rn.f32x2 %0, %1, %2, %0;" : "+l"(d) : "l"(a), "l"(b));
}
__device__ __forceinline__ ull dup2(float x) {
    ull r; asm("mov.b64 %0, {%1, %1};" : "=l"(r) : "f"(x)); return r;
}
__device__ __forceinline__ void unpack2(float &lo, float &hi, ull v) {
    asm("mov.b64 {%0, %1}, %2;" : "=f"(lo), "=f"(hi) : "l"(v));
}

// ---------------- device scratch (zero-initialized) ----------------
__device__ float g_vp[NSPLIT * FCLEN];
__device__ float g_RT[DPADB * NRELP];           // R^T ext: row200=1, 201+ =0
__device__ float g_Vmat[M1 * VPAD];             // pad cols stay zero
__device__ float g_w2p[KSPL_A * W2ROWS * W2PAD];// gemmA partials (rows>200 stay 0)
__device__ float g_W2[W2ROWS * W2PAD];
__device__ float g_qp[KSPL_B * NREL * WIN];
__device__ float g_q[NREL * WIN];
__device__ float g_c1[OC];
__device__ float g_scal0;

// ======== K1: v partials (16-way i-split) ===============================
__global__ void __launch_bounds__(256) k1_v(
        const float* __restrict__ fcw,
        const float* __restrict__ bn2g, const float* __restrict__ bn2v,
        const float* __restrict__ fc2w) {
    __shared__ float sa[ILEN];
    int tid = threadIdx.x;
    int isp = blockIdx.x / FBLK, fb = blockIdx.x % FBLK;
    if (tid < ILEN) {
        int i = isp * ILEN + tid;
        float s2 = bn2g[i] * rsqrtf(bn2v[i] + EPSBN);
        sa[tid] = s2 * fc2w[i];
    }
    __syncthreads();
    int f = fb * 256 + tid;
    const float* __restrict__ p = fcw + (size_t)isp * ILEN * FCLEN + f;
    float acc = 0.f;
#pragma unroll
    for (int ii = 0; ii < ILEN; ii++)
        acc = fmaf(sa[ii], p[(size_t)ii * FCLEN], acc);
    g_vp[isp * FCLEN + f] = acc;
}

// ======== KV: Vmat build + scal0 + R-transpose + ones row ===============
// blocks 0..31: channel Vmat; 32: scal0; 33..144: R^T tiles; 145: ones row
__global__ void __launch_bounds__(256) kv_build(
        const float* __restrict__ bn1g, const float* __restrict__ bn1b,
        const float* __restrict__ bn1m, const float* __restrict__ bn1v,
        const float* __restrict__ bn2g, const float* __restrict__ bn2b,
        const float* __restrict__ bn2m, const float* __restrict__ bn2v,
        const float* __restrict__ fc2w, const float* __restrict__ fc2b,
        const float* __restrict__ fcb,  const float* __restrict__ R) {
    int tid = threadIdx.x;
    int bid = blockIdx.x;
    if (bid < OC) {                          // ---- Vmat channel ----
        __shared__ float sv[WOUT];
        __shared__ float red[256];
        int o = bid;
        float inv1 = bn1g[o] * rsqrtf(bn1v[o] + EPSBN);
        float vsum = 0.f;
        for (int w = tid; w < WOUT; w += 256) {
            float s = 0.f;
#pragma unroll
            for (int sp = 0; sp < NSPLIT; sp++) s += g_vp[sp * FCLEN + o * WOUT + w];
            sv[w] = s * inv1;
            vsum += s;
        }
        red[tid] = vsum;
        __syncthreads();
        for (int s = 128; s; s >>= 1) { if (tid < s) red[tid] += red[tid + s]; __syncthreads(); }
        if (tid == 0) g_c1[o] = (bn1b[o] - bn1m[o] * inv1) * red[0];
        __syncthreads();
        for (int idx = tid; idx < FW * WIN; idx += 256) {
            int j = idx / WIN, t = idx - j * WIN;
            int w = t - j;
            g_Vmat[(o * FW + j) * VPAD + t] = ((unsigned)w < (unsigned)WOUT) ? sv[w] : 0.f;
        }
        return;
    }
    if (bid == OC) {                         // ---- scal0 ----
        __shared__ float red[256];
        float t = 0.f;
        for (int i = tid; i < WIN; i += 256) {
            float s2 = bn2g[i] * rsqrtf(bn2v[i] + EPSBN);
            float a  = s2 * fc2w[i];
            t += (bn2b[i] - bn2m[i] * s2) * fc2w[i] + a * fcb[i];
        }
        red[tid] = t;
        __syncthreads();
        for (int s = 128; s; s >>= 1) { if (tid < s) red[tid] += red[tid + s]; __syncthreads(); }
        if (tid == 0) g_scal0 = red[0] + fc2b[0];
        return;
    }
    if (bid == OC + 1 + 112) {               // ---- ones row (d=200) ----
        for (int i = tid; i < NRELP; i += 256) g_RT[200 * NRELP + i] = 1.0f;
        return;
    }
    // ---- R^T tile: 7 d-tiles x 16 rel-tiles ----
    __shared__ float tile[32][33];
    int tb = bid - (OC + 1);
    int dt = tb / 16, rt = tb % 16;
    int d0 = dt * 32, r0 = rt * 32;
    int tx = tid & 31, ty = tid >> 5;        // 8 rows per pass
    for (int rr = ty; rr < 32; rr += 8) {
        int rel = r0 + rr, d = d0 + tx;
        tile[rr][tx] = (rel < NREL && d < 200) ? R[rel * 200 + d] : 0.f;
    }
    __syncthreads();
    for (int rr = ty; rr < 32; rr += 8) {
        int d = d0 + rr, rel = r0 + tx;
        if (d < 200) g_RT[d * NRELP + rel] = tile[tx][rr];
    }
}

// ======== GEMM-A: W2[d][t] = sum_m fc1w_ext[m][d] * Vmat[m][t] ==========
// fc1w_ext row d=200 is fc1b. 32d x 64t tiles, K-split 12, FFMA2.
__global__ void __launch_bounds__(128) gemmA(
        const float* __restrict__ fc1w, const float* __restrict__ fc1b) {
    __shared__ float sA[KLEN_A][36];   // [m][d]
    __shared__ float sB[KLEN_A][68];   // [m][t]
    int tid = threadIdx.x;
    int d0 = blockIdx.x * 32;
    int t0 = blockIdx.y * 64;
    int m0 = blockIdx.z * KLEN_A;

    for (int i = tid; i < KLEN_A * 32; i += 128) {
        int kk = i >> 5, dd = i & 31;
        int d = d0 + dd, m = m0 + kk;
        float v = 0.f;
        if (d < 200) v = fc1w[m * 200 + d];
        else if (d == 200) v = fc1b[m];
        sA[kk][dd] = v;
    }
    for (int i = tid; i < KLEN_A * 16; i += 128) {
        int kk = i >> 4, c = i & 15;
        *(float4*)&sB[kk][c * 4] =
            *(const float4*)&g_Vmat[(size_t)(m0 + kk) * VPAD + t0 + c * 4];
    }
    __syncthreads();

    int tx = tid & 15, ty = tid >> 4;
    ull acc[2][4] = {};
#pragma unroll
    for (int kk = 0; kk < KLEN_A; kk++) {
        ull a01 = *(const ull*)&sA[kk][ty * 4];
        ull a23 = *(const ull*)&sA[kk][ty * 4 + 2];
        float4 b4 = *(const float4*)&sB[kk][tx * 4];
        ull bx = dup2(b4.x), by = dup2(b4.y), bz = dup2(b4.z), bw = dup2(b4.w);
        ffma2(acc[0][0], a01, bx); ffma2(acc[0][1], a01, by);
        ffma2(acc[0][2], a01, bz); ffma2(acc[0][3], a01, bw);
        ffma2(acc[1][0], a23, bx); ffma2(acc[1][1], a23, by);
        ffma2(acc[1][2], a23, bz); ffma2(acc[1][3], a23, bw);
    }
    float r[4][4];
#pragma unroll
    for (int n = 0; n < 4; n++) {
        unpack2(r[0][n], r[1][n], acc[0][n]);
        unpack2(r[2][n], r[3][n], acc[1][n]);
    }
    float* __restrict__ wp = g_w2p + (size_t)blockIdx.z * (W2ROWS * W2PAD);
    int gn = t0 + tx * 4;
#pragma unroll
    for (int mi = 0; mi < 4; mi++) {
        int d = d0 + ty * 4 + mi;
        if (d < 201) {
            float4 v = make_float4(r[mi][0], r[mi][1], r[mi][2], r[mi][3]);
            *(float4*)&wp[d * W2PAD + gn] = v;
        }
    }
}

// ======== FOLD-W2 =======================================================
__global__ void __launch_bounds__(256) fold_w2() {
    int idx = blockIdx.x * 256 + threadIdx.x;     // f4 index, 28672 total
    float4 s = make_float4(0.f, 0.f, 0.f, 0.f);
#pragma unroll
    for (int p = 0; p < KSPL_A; p++) {
        float4 t = ((const float4*)(g_w2p + (size_t)p * (W2ROWS * W2PAD)))[idx];
        s.x += t.x; s.y += t.y; s.z += t.z; s.w += t.w;
    }
    ((float4*)g_W2)[idx] = s;
}

// ======== GEMM-B: q[r][t] = sum_d RT[d][r] * W2[d][t] ===================
// 32rel x 64t tiles, K-split 8 (K=208), FFMA2.
__global__ void __launch_bounds__(128) gemmB() {
    __shared__ float sR[KLEN_B][36];
    __shared__ float sW[KLEN_B][68];
    int tid = threadIdx.x;
    int r0 = blockIdx.x * 32;
    int t0 = blockIdx.y * 64;
    int k0 = blockIdx.z * KLEN_B;

    for (int i = tid; i < KLEN_B * 8; i += 128) {
        int kk = i >> 3, c = i & 7;
        *(float4*)&sR[kk][c * 4] =
            *(const float4*)&g_RT[(size_t)(k0 + kk) * NRELP + r0 + c * 4];
    }
    for (int i = tid; i < KLEN_B * 16; i += 128) {
        int kk = i >> 4, c = i & 15;
        *(float4*)&sW[kk][c * 4] =
            *(const float4*)&g_W2[(size_t)(k0 + kk) * W2PAD + t0 + c * 4];
    }
    __syncthreads();

    int tx = tid & 15, ty = tid >> 4;
    ull acc[2][4] = {};
#pragma unroll
    for (int kk = 0; kk < KLEN_B; kk++) {
        ull a01 = *(const ull*)&sR[kk][ty * 4];
        ull a23 = *(const ull*)&sR[kk][ty * 4 + 2];
        float4 b4 = *(const float4*)&sW[kk][tx * 4];
        ull bx = dup2(b4.x), by = dup2(b4.y), bz = dup2(b4.z), bw = dup2(b4.w);
        ffma2(acc[0][0], a01, bx); ffma2(acc[0][1], a01, by);
        ffma2(acc[0][2], a01, bz); ffma2(acc[0][3], a01, bw);
        ffma2(acc[1][0], a23, bx); ffma2(acc[1][1], a23, by);
        ffma2(acc[1][2], a23, bz); ffma2(acc[1][3], a23, bw);
    }
    float r[4][4];
#pragma unroll
    for (int n = 0; n < 4; n++) {
        unpack2(r[0][n], r[1][n], acc[0][n]);
        unpack2(r[2][n], r[3][n], acc[1][n]);
    }
    float* __restrict__ qp = g_qp + (size_t)blockIdx.z * (NREL * WIN);
    int gn = t0 + tx * 4;
    if (gn < WIN) {
#pragma unroll
        for (int mi = 0; mi < 4; mi++) {
            int gm = r0 + ty * 4 + mi;
            if (gm < NREL) {
                float4 v = make_float4(r[mi][0], r[mi][1], r[mi][2], r[mi][3]);
                *(float4*)&qp[gm * WIN + gn] = v;
            }
        }
    }
}

// ======== FOLD-Q ========================================================
__global__ void __launch_bounds__(256) fold_q() {
    int idx = blockIdx.x * 256 + threadIdx.x;
    if (idx >= NREL * WIN / 4) return;
    float4 s = make_float4(0.f, 0.f, 0.f, 0.f);
#pragma unroll
    for (int p = 0; p < KSPL_B; p++) {
        float4 t = ((const float4*)(g_qp + (size_t)p * (NREL * WIN)))[idx];
        s.x += t.x; s.y += t.y; s.z += t.z; s.w += t.w;
    }
    ((float4*)g_q)[idx] = s;
}

// ======== K4: 2 warps per example =======================================
__global__ void __launch_bounds__(256) k4_main(
        const int* __restrict__ e1i, const int* __restrict__ ri,
        const int* __restrict__ e2i, const float* __restrict__ Et,
        const float* __restrict__ bn0g, const float* __restrict__ bn0b,
        const float* __restrict__ bn0m, const float* __restrict__ bn0v,
        const float* __restrict__ bias, float* __restrict__ out) {
    __shared__ float part[8];
    int tid = threadIdx.x;
    int lane = tid & 31;
    int half = (tid >> 5) & 1;
    int k = tid >> 6;
    int b = blockIdx.x * 4 + k;
    float s0 = bn0g[0] * rsqrtf(bn0v[0] + EPSBN);
    float c0 = bn0b[0] - bn0m[0] * s0;
    int r  = ri[b];
    int e  = half ? e2i[b] : e1i[b];
    const float4* __restrict__ E = (const float4*)(Et + (size_t)e * D1);
    const float4* __restrict__ Q = (const float4*)(g_q + r * WIN) + half * 50;
    float acc = half ? 0.f : g_c1[lane];
    {
        float4 ev = E[lane], qv = Q[lane];
        acc = fmaf(fmaf(s0, ev.x, c0), qv.x, acc);
        acc = fmaf(fmaf(s0, ev.y, c0), qv.y, acc);
        acc = fmaf(fmaf(s0, ev.z, c0), qv.z, acc);
        acc = fmaf(fmaf(s0, ev.w, c0), qv.w, acc);
    }
    if (lane < 18) {
        float4 ev = E[lane + 32], qv = Q[lane + 32];
        acc = fmaf(fmaf(s0, ev.x, c0), qv.x, acc);
        acc = fmaf(fmaf(s0, ev.y, c0), qv.y, acc);
        acc = fmaf(fmaf(s0, ev.z, c0), qv.z, acc);
        acc = fmaf(fmaf(s0, ev.w, c0), qv.w, acc);
    }
    for (int o = 16; o; o >>= 1) acc += __shfl_down_sync(0xffffffffu, acc, o);
    if (lane == 0) part[tid >> 5] = acc;
    __syncthreads();
    if ((tid & 63) == 0) {
        int w = tid >> 5;
        float z = part[w] + part[w + 1] + g_scal0;
        out[b] = tanhf(z) + bias[0];
    }
}

// ---------------- launch ------------------------------------------------
extern "C" void kernel_launch(void* const* d_in, const int* in_sizes, int n_in,
                              void* d_out, int out_size) {
    const int*   e1_idx  = (const int*)  d_in[0];
    const int*   r_idx   = (const int*)  d_in[1];
    const int*   e2_idx  = (const int*)  d_in[2];
    const float* E_table = (const float*)d_in[3];
    const float* R_table = (const float*)d_in[4];
    const float* bn0g    = (const float*)d_in[5];
    const float* bn0b    = (const float*)d_in[6];
    const float* bn0m    = (const float*)d_in[7];
    const float* bn0v    = (const float*)d_in[8];
    const float* fc1w    = (const float*)d_in[9];
    const float* fc1b    = (const float*)d_in[10];
    const float* bn1g    = (const float*)d_in[11];
    const float* bn1b    = (const float*)d_in[12];
    const float* bn1m    = (const float*)d_in[13];
    const float* bn1v    = (const float*)d_in[14];
    const float* fcw     = (const float*)d_in[15];
    const float* fcb     = (const float*)d_in[16];
    const float* bn2g    = (const float*)d_in[17];
    const float* bn2b    = (const float*)d_in[18];
    const float* bn2m    = (const float*)d_in[19];
    const float* bn2v    = (const float*)d_in[20];
    const float* fc2w    = (const float*)d_in[21];
    const float* fc2b    = (const float*)d_in[22];
    const float* bias    = (const float*)d_in[23];
    float* out = (float*)d_out;

    k1_v<<<NSPLIT * FBLK, 256>>>(fcw, bn2g, bn2v, fc2w);
    kv_build<<<OC + 1 + 112 + 1, 256>>>(bn1g, bn1b, bn1m, bn1v,
                                        bn2g, bn2b, bn2m, bn2v,
                                        fc2w, fc2b, fcb, R_table);
    gemmA<<<dim3(7, 7, KSPL_A), 128>>>(fc1w, fc1b);
    fold_w2<<<(W2ROWS * W2PAD / 4) / 256, 256>>>();
    gemmB<<<dim3(16, 7, KSPL_B), 128>>>();
    fold_q<<<(NREL * WIN / 4 + 255) / 256, 256>>>();
    k4_main<<<BATCH / 4, 256>>>(e1_idx, r_idx, e2_idx, E_table,
                                bn0g, bn0b, bn0m, bn0v, bias, out);
}